// round 3
// baseline (speedup 1.0000x reference)
#include <cuda_runtime.h>
#include <math.h>

#define NB 8192     // batch
#define ND 512      // dim
#define NK 4096     // codebook size
#define NL 16       // max word length

// ---------------- scratch (device globals) ---------------------------------
__device__ float g_S[(size_t)NB * NK];   // scores s[b,k] (approx, recurrence)
__device__ float g_G[(size_t)NK * NK];   // gram G[i,j] = c_i . c_j (approx)
__device__ float g_R[(size_t)NB * ND];   // tracked fp32 residual (bit-exact path)
__device__ float g_tn[NB];               // ||target|| per row
__device__ int   g_ck[NB];               // chosen k of previous step
__device__ float g_cc[NB];               // coef of previous step (0 if inactive)
__device__ int   g_seq[NB * NL];
__device__ int   g_act[NB * NL];

// ---------------- SGEMM (NT): C[M,N] = A[M,Kd] * B[N,Kd]^T -----------------
#define BM 128
#define BN 128
#define BK 16

__global__ __launch_bounds__(256, 2)
void sgemm_nt_kernel(const float* __restrict__ A, const float* __restrict__ Bm,
                     float* __restrict__ Cc, int M, int N, int Kd) {
    __shared__ float As[BK][BM + 4];
    __shared__ float Bs[BK][BN + 4];
    int tid = threadIdx.x;
    int tx = tid & 15;
    int ty = tid >> 4;
    int m0 = blockIdx.y * BM;
    int n0 = blockIdx.x * BN;

    float acc[8][8];
    #pragma unroll
    for (int i = 0; i < 8; i++)
        #pragma unroll
        for (int j = 0; j < 8; j++) acc[i][j] = 0.f;

    for (int d0 = 0; d0 < Kd; d0 += BK) {
        #pragma unroll
        for (int i = 0; i < 2; i++) {
            int idx = tid + i * 256;
            int r  = idx >> 2;
            int cg = (idx & 3) << 2;
            float4 va = *(const float4*)&A[(size_t)(m0 + r) * Kd + d0 + cg];
            As[cg + 0][r] = va.x; As[cg + 1][r] = va.y;
            As[cg + 2][r] = va.z; As[cg + 3][r] = va.w;
            float4 vb = *(const float4*)&Bm[(size_t)(n0 + r) * Kd + d0 + cg];
            Bs[cg + 0][r] = vb.x; Bs[cg + 1][r] = vb.y;
            Bs[cg + 2][r] = vb.z; Bs[cg + 3][r] = vb.w;
        }
        __syncthreads();

        #pragma unroll
        for (int d = 0; d < BK; d++) {
            float4 a0 = *(const float4*)&As[d][ty * 8];
            float4 a1 = *(const float4*)&As[d][ty * 8 + 4];
            float4 b0 = *(const float4*)&Bs[d][tx * 8];
            float4 b1 = *(const float4*)&Bs[d][tx * 8 + 4];
            float a[8] = {a0.x, a0.y, a0.z, a0.w, a1.x, a1.y, a1.z, a1.w};
            float bb[8] = {b0.x, b0.y, b0.z, b0.w, b1.x, b1.y, b1.z, b1.w};
            #pragma unroll
            for (int i = 0; i < 8; i++)
                #pragma unroll
                for (int j = 0; j < 8; j++)
                    acc[i][j] += a[i] * bb[j];
        }
        __syncthreads();
    }

    #pragma unroll
    for (int i = 0; i < 8; i++) {
        int m = m0 + ty * 8 + i;
        #pragma unroll
        for (int j = 0; j < 8; j += 4) {
            int n = n0 + tx * 8 + j;
            float4 v = make_float4(acc[i][j], acc[i][j + 1], acc[i][j + 2], acc[i][j + 3]);
            *(float4*)&Cc[(size_t)m * N + n] = v;
        }
    }
}

// ---------------- fused pursuit step ----------------------------------------
// Block b (256 threads):
//  1) apply previous step's residual update (unfused mul+sub, jax-bit-exact)
//     and compute ||r|| (fp64 accum)
//  2) apply previous step's S-row update (approx) while tracking top-2 of |S|
//  3) re-score the 2 candidates freshly: sequential fp32 FMA dot of
//     q = r/max(rho,1e-12) with codebook rows (mimics reference accumulation)
//  4) decide index/sign/active, emit symbol, stage next update
__global__ __launch_bounds__(256)
void step_kernel(const float* __restrict__ Cb, float decay, int t) {
    __shared__ float  s_q[ND];
    __shared__ double s_red[8];
    __shared__ float  s_v1[256], s_v2[256];
    __shared__ int    s_i1[256], s_i2[256];
    __shared__ float  s_dot[2];
    __shared__ float  s_rho;

    int b = blockIdx.x;
    int tid = threadIdx.x;
    float* rrow = g_R + (size_t)b * ND;
    float* srow = g_S + (size_t)b * NK;

    int kp = 0; float cp = 0.f;
    if (t > 0) { kp = g_ck[b]; cp = g_cc[b]; }

    // ---- phase 1: residual update + sumsq --------------------------------
    double ss = 0.0;
    #pragma unroll
    for (int i = 0; i < 2; i++) {
        int d = tid + i * 256;
        float r = rrow[d];
        if (cp != 0.f) {
            float c = __ldg(&Cb[(size_t)kp * ND + d]);
            r = __fsub_rn(r, __fmul_rn(cp, c));   // unfused: matches jax
            rrow[d] = r;
        }
        s_q[d] = r;
        ss += (double)r * (double)r;
    }
    #pragma unroll
    for (int o = 16; o > 0; o >>= 1) ss += __shfl_down_sync(0xffffffffu, ss, o);
    if ((tid & 31) == 0) s_red[tid >> 5] = ss;

    // ---- phase 2: S update + per-thread top-2 ----------------------------
    float v1 = -1.f, v2 = -1.f;
    int   i1 = 0,    i2 = 0;
    const float* grow = g_G + (size_t)kp * NK;
    #pragma unroll
    for (int it = 0; it < NK / 1024; it++) {
        int k = tid * 4 + it * 1024;
        float4 s4 = *(const float4*)&srow[k];
        if (cp != 0.f) {
            float4 g4 = __ldg((const float4*)&grow[k]);
            s4.x = fmaf(-cp, g4.x, s4.x);
            s4.y = fmaf(-cp, g4.y, s4.y);
            s4.z = fmaf(-cp, g4.z, s4.z);
            s4.w = fmaf(-cp, g4.w, s4.w);
            *(float4*)&srow[k] = s4;
        }
        float a;
        a = fabsf(s4.x); if (a > v1) { v2=v1;i2=i1; v1=a;i1=k;   } else if (a > v2) { v2=a;i2=k;   }
        a = fabsf(s4.y); if (a > v1) { v2=v1;i2=i1; v1=a;i1=k+1; } else if (a > v2) { v2=a;i2=k+1; }
        a = fabsf(s4.z); if (a > v1) { v2=v1;i2=i1; v1=a;i1=k+2; } else if (a > v2) { v2=a;i2=k+2; }
        a = fabsf(s4.w); if (a > v1) { v2=v1;i2=i1; v1=a;i1=k+3; } else if (a > v2) { v2=a;i2=k+3; }
    }
    s_v1[tid] = v1; s_i1[tid] = i1;
    s_v2[tid] = v2; s_i2[tid] = i2;
    __syncthreads();

    // ---- block reduce top-2 (tie -> smaller index) -----------------------
    for (int s = 128; s > 0; s >>= 1) {
        if (tid < s) {
            float a1 = s_v1[tid],   a2 = s_v2[tid];
            int   ia1 = s_i1[tid],  ia2 = s_i2[tid];
            float b1 = s_v1[tid+s], b2 = s_v2[tid+s];
            int   ib1 = s_i1[tid+s],ib2 = s_i2[tid+s];
            // top1 of union
            float t1v; int t1i; float lo_v; int lo_i;
            if (b1 > a1 || (b1 == a1 && ib1 < ia1)) { t1v=b1; t1i=ib1; lo_v=a1; lo_i=ia1; }
            else                                    { t1v=a1; t1i=ia1; lo_v=b1; lo_i=ib1; }
            // top2 = max( loser-of-top1s , max(a2,b2) )
            float m2v; int m2i;
            if (b2 > a2 || (b2 == a2 && ib2 < ia2)) { m2v=b2; m2i=ib2; }
            else                                    { m2v=a2; m2i=ia2; }
            float t2v; int t2i;
            if (m2v > lo_v || (m2v == lo_v && m2i < lo_i)) { t2v=m2v; t2i=m2i; }
            else                                            { t2v=lo_v; t2i=lo_i; }
            s_v1[tid]=t1v; s_i1[tid]=t1i;
            s_v2[tid]=t2v; s_i2[tid]=t2i;
        }
        __syncthreads();
    }

    // ---- rho -------------------------------------------------------------
    if (tid == 0) {
        double tot = s_red[0]+s_red[1]+s_red[2]+s_red[3]
                   + s_red[4]+s_red[5]+s_red[6]+s_red[7];
        float rho = sqrtf((float)tot);
        s_rho = rho;
        if (t == 0) g_tn[b] = rho;
    }
    __syncthreads();

    // ---- normalize q = r / max(rho, 1e-12) -------------------------------
    {
        float rho = s_rho;
        float den = fmaxf(rho, 1e-12f);
        #pragma unroll
        for (int i = 0; i < 2; i++) {
            int d = tid + i * 256;
            s_q[d] = __fdiv_rn(s_q[d], den);
        }
    }
    __syncthreads();

    // ---- precise re-score of both candidates (sequential fp32 FMA) ------
    if (tid < 2) {
        int k = (tid == 0) ? s_i1[0] : s_i2[0];
        const float* crow = Cb + (size_t)k * ND;
        float acc = 0.f;
        #pragma unroll 8
        for (int d = 0; d < ND; d++)
            acc = fmaf(s_q[d], __ldg(&crow[d]), acc);
        s_dot[tid] = acc;
    }
    __syncthreads();

    // ---- decide ----------------------------------------------------------
    if (tid == 0) {
        int   kA = s_i1[0], kB = s_i2[0];
        float sA = s_dot[0], sB = s_dot[1];
        float aA = fabsf(sA), aB = fabsf(sB);
        int bk; float sb;
        if (aB > aA || (aB == aA && kB < kA)) { bk = kB; sb = sB; }
        else                                  { bk = kA; sb = sA; }
        float rho = s_rho;
        float tn  = (t == 0) ? rho : g_tn[b];
        bool active = (rho >= 0.01f) && (tn >= 1e-8f);
        float sgn = (sb >= 0.f) ? 1.f : -1.f;
        int sidx  = (sb >= 0.f) ? bk : -(bk + 1);
        g_seq[b * NL + t] = active ? sidx : 0;
        g_act[b * NL + t] = active ? 1 : 0;
        g_ck[b] = bk;
        g_cc[b] = active ? __fmul_rn(sgn, decay) : 0.f;
    }
}

// ---------------- finalize ---------------------------------------------------
// out layout (float32): [0, B*L) seq ; [B*L, 2*B*L) mask ; [2*B*L, ..) residual
// Residual recomputed from targets with the exact same unfused arithmetic and
// decay values as the incremental path (bit-identical).
__global__ void finalize_kernel(const float* __restrict__ T,
                                const float* __restrict__ C,
                                float* __restrict__ out) {
    int b = blockIdx.x;
    int tid = threadIdx.x;  // 128
    float4 r = *(const float4*)&T[(size_t)b * ND + tid * 4];
    double dd = 1.0;
    #pragma unroll
    for (int t = 0; t < NL; t++) {
        dd *= 0.95;
        float decay = (float)dd;
        if (g_act[b * NL + t]) {
            int siv = g_seq[b * NL + t];
            int k = (siv >= 0) ? siv : (-siv - 1);
            float sgn = (siv >= 0) ? 1.f : -1.f;
            float coef = __fmul_rn(sgn, decay);
            float4 c = *(const float4*)&C[(size_t)k * ND + tid * 4];
            r.x = __fsub_rn(r.x, __fmul_rn(coef, c.x));
            r.y = __fsub_rn(r.y, __fmul_rn(coef, c.y));
            r.z = __fsub_rn(r.z, __fmul_rn(coef, c.z));
            r.w = __fsub_rn(r.w, __fmul_rn(coef, c.w));
        }
    }
    float* out_res = out + (size_t)2 * NB * NL;
    *(float4*)&out_res[(size_t)b * ND + tid * 4] = r;
    if (tid < NL) {
        out[b * NL + tid] = (float)g_seq[b * NL + tid];
        out[NB * NL + b * NL + tid] = g_act[b * NL + tid] ? 1.f : 0.f;
    }
}

// ---------------- launch ----------------------------------------------------
extern "C" void kernel_launch(void* const* d_in, const int* in_sizes, int n_in,
                              void* d_out, int out_size) {
    const float* targets  = (const float*)d_in[0];  // [8192, 512]
    const float* codebook = (const float*)d_in[1];  // [4096, 512]
    float* out = (float*)d_out;

    float *pS, *pG, *pR;
    cudaGetSymbolAddress((void**)&pS, g_S);
    cudaGetSymbolAddress((void**)&pG, g_G);
    cudaGetSymbolAddress((void**)&pR, g_R);

    // residual starts as targets
    cudaMemcpyAsync(pR, targets, (size_t)NB * ND * sizeof(float),
                    cudaMemcpyDeviceToDevice);

    dim3 gS(NK / BN, NB / BM);
    sgemm_nt_kernel<<<gS, 256>>>(targets, codebook, pS, NB, NK, ND);

    dim3 gG(NK / BN, NK / BM);
    sgemm_nt_kernel<<<gG, 256>>>(codebook, codebook, pG, NK, NK, ND);

    double dd = 1.0;
    for (int t = 0; t < NL; t++) {
        dd *= 0.95;
        step_kernel<<<NB, 256>>>(codebook, (float)dd, t);
    }

    finalize_kernel<<<NB, 128>>>(targets, codebook, out);
}

// round 6
// speedup vs baseline: 1.2251x; 1.2251x over previous
#include <cuda_runtime.h>
#include <math.h>

#define NB 8192     // batch
#define ND 512      // dim
#define NK 4096     // codebook size
#define NL 16       // max word length

// ---------------- scratch (device globals) ---------------------------------
__device__ float g_S[(size_t)NB * NK];   // scores s0[b,k] (GEMM output)
__device__ float g_G[(size_t)NK * NK];   // gram G[i,j] = c_i . c_j

// ---------------- f32x2 packed helpers (bit-exact lane-wise fma.rn.f32) ----
__device__ __forceinline__ unsigned long long ffma2(unsigned long long a,
                                                    unsigned long long b,
                                                    unsigned long long c) {
    unsigned long long d;
    asm("fma.rn.f32x2 %0, %1, %2, %3;" : "=l"(d) : "l"(a), "l"(b), "l"(c));
    return d;
}
__device__ __forceinline__ unsigned long long dup2(float x) {
    unsigned long long d;
    unsigned int xi = __float_as_uint(x);
    asm("mov.b64 %0, {%1, %1};" : "=l"(d) : "r"(xi));
    return d;
}

// ---------------- SGEMM (NT): C[M,N] = A[M,Kd] * B[N,Kd]^T -----------------
// 128x128 tile, BK=16, 256 threads, 8x8 microtile via packed f32x2 FFMA2.
// Per-element accumulation chain (ascending d) identical to scalar version:
// results are bit-exact fp32.
#define BM 128
#define BN 128
#define BK 16

__global__ __launch_bounds__(256, 2)
void sgemm_nt_kernel(const float* __restrict__ A, const float* __restrict__ Bm,
                     float* __restrict__ Cc, int M, int N, int Kd) {
    __shared__ float As[BK][BM + 4];
    __shared__ float Bs[BK][BN + 4];
    int tid = threadIdx.x;
    int tx = tid & 15;
    int ty = tid >> 4;
    int m0 = blockIdx.y * BM;
    int n0 = blockIdx.x * BN;

    unsigned long long acc2[8][4];   // 8 rows x 4 packed pairs (= 8 cols)
    #pragma unroll
    for (int i = 0; i < 8; i++)
        #pragma unroll
        for (int j = 0; j < 4; j++) acc2[i][j] = 0ull;

    for (int d0 = 0; d0 < Kd; d0 += BK) {
        #pragma unroll
        for (int i = 0; i < 2; i++) {
            int idx = tid + i * 256;
            int r  = idx >> 2;
            int cg = (idx & 3) << 2;
            float4 va = *(const float4*)&A[(size_t)(m0 + r) * Kd + d0 + cg];
            As[cg + 0][r] = va.x; As[cg + 1][r] = va.y;
            As[cg + 2][r] = va.z; As[cg + 3][r] = va.w;
            float4 vb = *(const float4*)&Bm[(size_t)(n0 + r) * Kd + d0 + cg];
            Bs[cg + 0][r] = vb.x; Bs[cg + 1][r] = vb.y;
            Bs[cg + 2][r] = vb.z; Bs[cg + 3][r] = vb.w;
        }
        __syncthreads();

        #pragma unroll
        for (int d = 0; d < BK; d++) {
            float4 a0 = *(const float4*)&As[d][ty * 8];
            float4 a1 = *(const float4*)&As[d][ty * 8 + 4];
            const unsigned long long* bp =
                (const unsigned long long*)&Bs[d][tx * 8];
            unsigned long long b0 = bp[0], b1 = bp[1], b2 = bp[2], b3 = bp[3];
            float a[8] = {a0.x, a0.y, a0.z, a0.w, a1.x, a1.y, a1.z, a1.w};
            #pragma unroll
            for (int i = 0; i < 8; i++) {
                unsigned long long ad = dup2(a[i]);
                acc2[i][0] = ffma2(ad, b0, acc2[i][0]);
                acc2[i][1] = ffma2(ad, b1, acc2[i][1]);
                acc2[i][2] = ffma2(ad, b2, acc2[i][2]);
                acc2[i][3] = ffma2(ad, b3, acc2[i][3]);
            }
        }
        __syncthreads();
    }

    #pragma unroll
    for (int i = 0; i < 8; i++) {
        int m = m0 + ty * 8 + i;
        #pragma unroll
        for (int j = 0; j < 2; j++) {
            int n = n0 + tx * 8 + j * 4;
            float2 p0, p1;
            *(unsigned long long*)&p0 = acc2[i][j * 2 + 0];
            *(unsigned long long*)&p1 = acc2[i][j * 2 + 1];
            float4 v = make_float4(p0.x, p0.y, p1.x, p1.y);
            *(float4*)&Cc[(size_t)m * N + n] = v;
        }
    }
}

// ---------------- top-2 merge (value desc, tie -> smaller index) -----------
__device__ __forceinline__ void top2_merge(float& v1, int& i1, float& v2, int& i2,
                                           float w1, int j1, float w2, int j2) {
    if (w1 > v1 || (w1 == v1 && j1 < i1)) {
        float lv = v1; int li = i1;
        v1 = w1; i1 = j1;
        if (lv > w2 || (lv == w2 && li < j2)) { v2 = lv; i2 = li; }
        else                                  { v2 = w2; i2 = j2; }
    } else {
        if (w1 > v2 || (w1 == v2 && j1 < i2)) { v2 = w1; i2 = j1; }
    }
}

// ---------------- fused pursuit: all 16 steps + finalize in one kernel -----
// Block b (256 threads): S row in smem, residual in smem.
// Decision-path arithmetic byte-identical to round-3 kernels. Epilogue
// applies the FINAL step's residual contribution (lazy-update chain is
// one step behind inside the loop) before writing the residual out.
__global__ __launch_bounds__(256)
void pursuit_kernel(const float* __restrict__ T, const float* __restrict__ Cb,
                    const float* __restrict__ G, const float* __restrict__ S0,
                    float* __restrict__ out) {
    __shared__ float  sS[NK];       // 16 KB: score row
    __shared__ float  s_r[ND];      // residual
    __shared__ float  s_q[ND];      // q = r / max(rho,1e-12)
    __shared__ double s_red[8];
    __shared__ float  s_wv1[8], s_wv2[8];
    __shared__ int    s_wi1[8], s_wi2[8];
    __shared__ float  s_dot[2];
    __shared__ float  s_rho, s_tn, s_coef;
    __shared__ int    s_kA, s_kB, s_k;

    int b = blockIdx.x;
    int tid = threadIdx.x;
    int lane = tid & 31;
    int wid = tid >> 5;

    // load S row and residual (= targets row)
    #pragma unroll
    for (int it = 0; it < 4; it++) {
        int k = tid * 4 + it * 1024;
        *(float4*)&sS[k] = *(const float4*)&S0[(size_t)b * NK + k];
    }
    s_r[tid]       = T[(size_t)b * ND + tid];
    s_r[tid + 256] = T[(size_t)b * ND + tid + 256];
    __syncthreads();

    int kp = 0; float cp = 0.f;
    double dd = 1.0;

    for (int t = 0; t < NL; t++) {
        dd *= 0.95;                 // double cumprod, same bits as host path
        float decay = (float)dd;

        // ---- phase 1: residual update + fp64 sumsq (round-3 structure) ---
        double ss = 0.0;
        #pragma unroll
        for (int i = 0; i < 2; i++) {
            int d = tid + i * 256;
            float r = s_r[d];
            if (cp != 0.f) {
                float c = __ldg(&Cb[(size_t)kp * ND + d]);
                r = __fsub_rn(r, __fmul_rn(cp, c));   // unfused: matches jax
                s_r[d] = r;
            }
            s_q[d] = r;
            ss += (double)r * (double)r;
        }
        #pragma unroll
        for (int o = 16; o > 0; o >>= 1)
            ss += __shfl_down_sync(0xffffffffu, ss, o);
        if (lane == 0) s_red[wid] = ss;

        // ---- phase 2: S update (fmaf, identical) + per-thread top-2 ------
        float v1 = -1.f, v2 = -1.f;
        int   i1 = 0,    i2 = 0;
        const float* grow = G + (size_t)kp * NK;
        #pragma unroll
        for (int it = 0; it < 4; it++) {
            int k = tid * 4 + it * 1024;
            float4 s4 = *(float4*)&sS[k];
            if (cp != 0.f) {
                float4 g4 = __ldg((const float4*)&grow[k]);
                s4.x = fmaf(-cp, g4.x, s4.x);
                s4.y = fmaf(-cp, g4.y, s4.y);
                s4.z = fmaf(-cp, g4.z, s4.z);
                s4.w = fmaf(-cp, g4.w, s4.w);
                *(float4*)&sS[k] = s4;
            }
            float a;
            a = fabsf(s4.x); if (a > v1) { v2=v1;i2=i1; v1=a;i1=k;   } else if (a > v2) { v2=a;i2=k;   }
            a = fabsf(s4.y); if (a > v1) { v2=v1;i2=i1; v1=a;i1=k+1; } else if (a > v2) { v2=a;i2=k+1; }
            a = fabsf(s4.z); if (a > v1) { v2=v1;i2=i1; v1=a;i1=k+2; } else if (a > v2) { v2=a;i2=k+2; }
            a = fabsf(s4.w); if (a > v1) { v2=v1;i2=i1; v1=a;i1=k+3; } else if (a > v2) { v2=a;i2=k+3; }
        }
        // warp-level top-2 reduce (shuffle butterfly)
        #pragma unroll
        for (int o = 16; o > 0; o >>= 1) {
            float w1 = __shfl_xor_sync(0xffffffffu, v1, o);
            int   j1 = __shfl_xor_sync(0xffffffffu, i1, o);
            float w2 = __shfl_xor_sync(0xffffffffu, v2, o);
            int   j2 = __shfl_xor_sync(0xffffffffu, i2, o);
            top2_merge(v1, i1, v2, i2, w1, j1, w2, j2);
        }
        if (lane == 0) {
            s_wv1[wid] = v1; s_wi1[wid] = i1;
            s_wv2[wid] = v2; s_wi2[wid] = i2;
        }
        __syncthreads();

        // ---- rho + final top-2 combine (tid 0) ---------------------------
        if (tid == 0) {
            double tot = s_red[0]+s_red[1]+s_red[2]+s_red[3]
                       + s_red[4]+s_red[5]+s_red[6]+s_red[7];
            float rho = sqrtf((float)tot);
            s_rho = rho;
            if (t == 0) s_tn = rho;

            float a1 = s_wv1[0], a2 = s_wv2[0];
            int   x1 = s_wi1[0], x2 = s_wi2[0];
            #pragma unroll
            for (int w = 1; w < 8; w++)
                top2_merge(a1, x1, a2, x2, s_wv1[w], s_wi1[w], s_wv2[w], s_wi2[w]);
            s_kA = x1; s_kB = x2;
        }
        __syncthreads();

        // ---- q = r / max(rho, 1e-12) (elementwise, identical) ------------
        {
            float den = fmaxf(s_rho, 1e-12f);
            #pragma unroll
            for (int i = 0; i < 2; i++) {
                int d = tid + i * 256;
                s_q[d] = __fdiv_rn(s_q[d], den);
            }
        }
        __syncthreads();

        // ---- precise re-score: 2 threads, sequential fp32 FMA (identical)
        if (tid < 2) {
            int k = (tid == 0) ? s_kA : s_kB;
            const float* crow = Cb + (size_t)k * ND;
            float acc = 0.f;
            #pragma unroll 8
            for (int d = 0; d < ND; d++)
                acc = fmaf(s_q[d], __ldg(&crow[d]), acc);
            s_dot[tid] = acc;
        }
        __syncthreads();

        // ---- decide (identical logic) ------------------------------------
        if (tid == 0) {
            int   kA = s_kA, kB = s_kB;
            float sA = s_dot[0], sB = s_dot[1];
            float aA = fabsf(sA), aB = fabsf(sB);
            int bk; float sb;
            if (aB > aA || (aB == aA && kB < kA)) { bk = kB; sb = sB; }
            else                                  { bk = kA; sb = sA; }
            float rho = s_rho;
            float tn  = s_tn;
            bool active = (rho >= 0.01f) && (tn >= 1e-8f);
            float sgn = (sb >= 0.f) ? 1.f : -1.f;
            int sidx  = (sb >= 0.f) ? bk : -(bk + 1);
            out[b * NL + t]           = (float)(active ? sidx : 0);
            out[NB * NL + b * NL + t] = active ? 1.f : 0.f;
            s_k = bk;
            s_coef = active ? __fmul_rn(sgn, decay) : 0.f;
        }
        __syncthreads();
        kp = s_k;
        cp = s_coef;
    }

    // ---- epilogue: apply FINAL step's contribution (lazy chain catch-up) --
    // Identical arithmetic to the in-loop update; completes the op-for-op
    // match with the reference's per-step residual sequence.
    float r0 = s_r[tid];
    float r1 = s_r[tid + 256];
    if (cp != 0.f) {
        float c0 = __ldg(&Cb[(size_t)kp * ND + tid]);
        float c1 = __ldg(&Cb[(size_t)kp * ND + tid + 256]);
        r0 = __fsub_rn(r0, __fmul_rn(cp, c0));
        r1 = __fsub_rn(r1, __fmul_rn(cp, c1));
    }
    float* out_res = out + (size_t)2 * NB * NL;
    out_res[(size_t)b * ND + tid]       = r0;
    out_res[(size_t)b * ND + tid + 256] = r1;
}

// ---------------- launch ----------------------------------------------------
extern "C" void kernel_launch(void* const* d_in, const int* in_sizes, int n_in,
                              void* d_out, int out_size) {
    const float* targets  = (const float*)d_in[0];  // [8192, 512]
    const float* codebook = (const float*)d_in[1];  // [4096, 512]
    float* out = (float*)d_out;

    float *pS, *pG;
    cudaGetSymbolAddress((void**)&pS, g_S);
    cudaGetSymbolAddress((void**)&pG, g_G);

    dim3 gS(NK / BN, NB / BM);
    sgemm_nt_kernel<<<gS, 256>>>(targets, codebook, pS, NB, NK, ND);

    dim3 gG(NK / BN, NK / BM);
    sgemm_nt_kernel<<<gG, 256>>>(codebook, codebook, pG, NK, NK, ND);

    pursuit_kernel<<<NB, 256>>>(targets, codebook, pG, pS, out);
}

// round 7
// speedup vs baseline: 1.8072x; 1.4752x over previous
#include <cuda_runtime.h>
#include <math.h>

#define NB 8192     // batch
#define ND 512      // dim
#define NK 4096     // codebook size
#define NL 16       // max word length

// ---------------- scratch (device globals) ---------------------------------
__device__ float g_S[(size_t)NB * NK];   // scores s0[b,k] (GEMM output)
__device__ float g_G[(size_t)NK * NK];   // gram G[i,j] = c_i . c_j

// ---------------- f32x2 packed helpers (bit-exact lane-wise fma.rn.f32) ----
__device__ __forceinline__ unsigned long long ffma2(unsigned long long a,
                                                    unsigned long long b,
                                                    unsigned long long c) {
    unsigned long long d;
    asm("fma.rn.f32x2 %0, %1, %2, %3;" : "=l"(d) : "l"(a), "l"(b), "l"(c));
    return d;
}
__device__ __forceinline__ unsigned long long dup2(float x) {
    unsigned long long d;
    unsigned int xi = __float_as_uint(x);
    asm("mov.b64 %0, {%1, %1};" : "=l"(d) : "r"(xi));
    return d;
}

// ---------------- SGEMM (NT): C[M,N] = A[M,Kd] * B[N,Kd]^T -----------------
#define BM 128
#define BN 128
#define BK 16

__global__ __launch_bounds__(256, 2)
void sgemm_nt_kernel(const float* __restrict__ A, const float* __restrict__ Bm,
                     float* __restrict__ Cc, int M, int N, int Kd) {
    __shared__ float As[BK][BM + 4];
    __shared__ float Bs[BK][BN + 4];
    int tid = threadIdx.x;
    int tx = tid & 15;
    int ty = tid >> 4;
    int m0 = blockIdx.y * BM;
    int n0 = blockIdx.x * BN;

    unsigned long long acc2[8][4];   // 8 rows x 4 packed pairs (= 8 cols)
    #pragma unroll
    for (int i = 0; i < 8; i++)
        #pragma unroll
        for (int j = 0; j < 4; j++) acc2[i][j] = 0ull;

    for (int d0 = 0; d0 < Kd; d0 += BK) {
        #pragma unroll
        for (int i = 0; i < 2; i++) {
            int idx = tid + i * 256;
            int r  = idx >> 2;
            int cg = (idx & 3) << 2;
            float4 va = *(const float4*)&A[(size_t)(m0 + r) * Kd + d0 + cg];
            As[cg + 0][r] = va.x; As[cg + 1][r] = va.y;
            As[cg + 2][r] = va.z; As[cg + 3][r] = va.w;
            float4 vb = *(const float4*)&Bm[(size_t)(n0 + r) * Kd + d0 + cg];
            Bs[cg + 0][r] = vb.x; Bs[cg + 1][r] = vb.y;
            Bs[cg + 2][r] = vb.z; Bs[cg + 3][r] = vb.w;
        }
        __syncthreads();

        #pragma unroll
        for (int d = 0; d < BK; d++) {
            float4 a0 = *(const float4*)&As[d][ty * 8];
            float4 a1 = *(const float4*)&As[d][ty * 8 + 4];
            const unsigned long long* bp =
                (const unsigned long long*)&Bs[d][tx * 8];
            unsigned long long b0 = bp[0], b1 = bp[1], b2 = bp[2], b3 = bp[3];
            float a[8] = {a0.x, a0.y, a0.z, a0.w, a1.x, a1.y, a1.z, a1.w};
            #pragma unroll
            for (int i = 0; i < 8; i++) {
                unsigned long long ad = dup2(a[i]);
                acc2[i][0] = ffma2(ad, b0, acc2[i][0]);
                acc2[i][1] = ffma2(ad, b1, acc2[i][1]);
                acc2[i][2] = ffma2(ad, b2, acc2[i][2]);
                acc2[i][3] = ffma2(ad, b3, acc2[i][3]);
            }
        }
        __syncthreads();
    }

    #pragma unroll
    for (int i = 0; i < 8; i++) {
        int m = m0 + ty * 8 + i;
        #pragma unroll
        for (int j = 0; j < 2; j++) {
            int n = n0 + tx * 8 + j * 4;
            float2 p0, p1;
            *(unsigned long long*)&p0 = acc2[i][j * 2 + 0];
            *(unsigned long long*)&p1 = acc2[i][j * 2 + 1];
            float4 v = make_float4(p0.x, p0.y, p1.x, p1.y);
            *(float4*)&Cc[(size_t)m * N + n] = v;
        }
    }
}

// ---------------- top-2 merge (value desc, tie -> smaller index) -----------
__device__ __forceinline__ void top2_merge(float& v1, int& i1, float& v2, int& i2,
                                           float w1, int j1, float w2, int j2) {
    if (w1 > v1 || (w1 == v1 && j1 < i1)) {
        float lv = v1; int li = i1;
        v1 = w1; i1 = j1;
        if (lv > w2 || (lv == w2 && li < j2)) { v2 = lv; i2 = li; }
        else                                  { v2 = w2; i2 = j2; }
    } else {
        if (w1 > v2 || (w1 == v2 && j1 < i2)) { v2 = w1; i2 = j1; }
    }
}

// ---------------- fused pursuit: all 16 steps + finalize in one kernel -----
// Same decision arithmetic as the passing round-6 kernel, but the 2-thread
// serial rescore now reads candidate codebook rows from SHARED memory
// (staged by all 256 threads in parallel) instead of chasing L2 latency
// from global — identical values in identical fmaf order, ~7x faster chain.
__global__ __launch_bounds__(256)
void pursuit_kernel(const float* __restrict__ T, const float* __restrict__ Cb,
                    const float* __restrict__ G, const float* __restrict__ S0,
                    float* __restrict__ out) {
    __shared__ float  sS[NK];       // 16 KB: score row
    __shared__ float  s_r[ND];      // residual
    __shared__ float  s_q[ND];      // q = r / max(rho,1e-12)
    __shared__ float  s_cA[ND];     // candidate A codebook row
    __shared__ float  s_cB[ND];     // candidate B codebook row
    __shared__ double s_red[8];
    __shared__ float  s_wv1[8], s_wv2[8];
    __shared__ int    s_wi1[8], s_wi2[8];
    __shared__ float  s_dot[2];
    __shared__ float  s_rho, s_tn, s_coef;
    __shared__ int    s_kA, s_kB, s_k;

    int b = blockIdx.x;
    int tid = threadIdx.x;
    int lane = tid & 31;
    int wid = tid >> 5;

    // load S row and residual (= targets row)
    #pragma unroll
    for (int it = 0; it < 4; it++) {
        int k = tid * 4 + it * 1024;
        *(float4*)&sS[k] = *(const float4*)&S0[(size_t)b * NK + k];
    }
    s_r[tid]       = T[(size_t)b * ND + tid];
    s_r[tid + 256] = T[(size_t)b * ND + tid + 256];
    __syncthreads();

    int kp = 0; float cp = 0.f;
    double dd = 1.0;

    for (int t = 0; t < NL; t++) {
        dd *= 0.95;                 // double cumprod, same bits as host path
        float decay = (float)dd;

        // ---- phase 1: residual update + fp64 sumsq -----------------------
        double ss = 0.0;
        #pragma unroll
        for (int i = 0; i < 2; i++) {
            int d = tid + i * 256;
            float r = s_r[d];
            if (cp != 0.f) {
                float c = __ldg(&Cb[(size_t)kp * ND + d]);
                r = __fsub_rn(r, __fmul_rn(cp, c));   // unfused: matches jax
                s_r[d] = r;
            }
            s_q[d] = r;
            ss += (double)r * (double)r;
        }
        #pragma unroll
        for (int o = 16; o > 0; o >>= 1)
            ss += __shfl_down_sync(0xffffffffu, ss, o);
        if (lane == 0) s_red[wid] = ss;

        // ---- phase 2: S update (fmaf, identical) + per-thread top-2 ------
        float v1 = -1.f, v2 = -1.f;
        int   i1 = 0,    i2 = 0;
        const float* grow = G + (size_t)kp * NK;
        #pragma unroll
        for (int it = 0; it < 4; it++) {
            int k = tid * 4 + it * 1024;
            float4 s4 = *(float4*)&sS[k];
            if (cp != 0.f) {
                float4 g4 = __ldg((const float4*)&grow[k]);
                s4.x = fmaf(-cp, g4.x, s4.x);
                s4.y = fmaf(-cp, g4.y, s4.y);
                s4.z = fmaf(-cp, g4.z, s4.z);
                s4.w = fmaf(-cp, g4.w, s4.w);
                *(float4*)&sS[k] = s4;
            }
            float a;
            a = fabsf(s4.x); if (a > v1) { v2=v1;i2=i1; v1=a;i1=k;   } else if (a > v2) { v2=a;i2=k;   }
            a = fabsf(s4.y); if (a > v1) { v2=v1;i2=i1; v1=a;i1=k+1; } else if (a > v2) { v2=a;i2=k+1; }
            a = fabsf(s4.z); if (a > v1) { v2=v1;i2=i1; v1=a;i1=k+2; } else if (a > v2) { v2=a;i2=k+2; }
            a = fabsf(s4.w); if (a > v1) { v2=v1;i2=i1; v1=a;i1=k+3; } else if (a > v2) { v2=a;i2=k+3; }
        }
        // warp-level top-2 reduce (shuffle butterfly)
        #pragma unroll
        for (int o = 16; o > 0; o >>= 1) {
            float w1 = __shfl_xor_sync(0xffffffffu, v1, o);
            int   j1 = __shfl_xor_sync(0xffffffffu, i1, o);
            float w2 = __shfl_xor_sync(0xffffffffu, v2, o);
            int   j2 = __shfl_xor_sync(0xffffffffu, i2, o);
            top2_merge(v1, i1, v2, i2, w1, j1, w2, j2);
        }
        if (lane == 0) {
            s_wv1[wid] = v1; s_wi1[wid] = i1;
            s_wv2[wid] = v2; s_wi2[wid] = i2;
        }
        __syncthreads();

        // ---- rho + final top-2 combine (tid 0) ---------------------------
        if (tid == 0) {
            double tot = s_red[0]+s_red[1]+s_red[2]+s_red[3]
                       + s_red[4]+s_red[5]+s_red[6]+s_red[7];
            float rho = sqrtf((float)tot);
            s_rho = rho;
            if (t == 0) s_tn = rho;

            float a1 = s_wv1[0], a2 = s_wv2[0];
            int   x1 = s_wi1[0], x2 = s_wi2[0];
            #pragma unroll
            for (int w = 1; w < 8; w++)
                top2_merge(a1, x1, a2, x2, s_wv1[w], s_wi1[w], s_wv2[w], s_wi2[w]);
            s_kA = x1; s_kB = x2;
        }
        __syncthreads();

        // ---- q = r / max(rho,1e-12) + parallel stage of candidate rows ---
        {
            float den = fmaxf(s_rho, 1e-12f);
            int kA = s_kA, kB = s_kB;
            #pragma unroll
            for (int i = 0; i < 2; i++) {
                int d = tid + i * 256;
                s_q[d] = __fdiv_rn(s_q[d], den);
                s_cA[d] = __ldg(&Cb[(size_t)kA * ND + d]);
                s_cB[d] = __ldg(&Cb[(size_t)kB * ND + d]);
            }
        }
        __syncthreads();

        // ---- precise re-score: 2 threads, sequential fp32 FMA ------------
        // identical fmaf sequence on identical values (now smem-sourced)
        if (tid < 2) {
            const float* crow = (tid == 0) ? s_cA : s_cB;
            float acc = 0.f;
            #pragma unroll 8
            for (int d = 0; d < ND; d++)
                acc = fmaf(s_q[d], crow[d], acc);
            s_dot[tid] = acc;
        }
        __syncthreads();

        // ---- decide (identical logic) ------------------------------------
        if (tid == 0) {
            int   kA = s_kA, kB = s_kB;
            float sA = s_dot[0], sB = s_dot[1];
            float aA = fabsf(sA), aB = fabsf(sB);
            int bk; float sb;
            if (aB > aA || (aB == aA && kB < kA)) { bk = kB; sb = sB; }
            else                                  { bk = kA; sb = sA; }
            float rho = s_rho;
            float tn  = s_tn;
            bool active = (rho >= 0.01f) && (tn >= 1e-8f);
            float sgn = (sb >= 0.f) ? 1.f : -1.f;
            int sidx  = (sb >= 0.f) ? bk : -(bk + 1);
            out[b * NL + t]           = (float)(active ? sidx : 0);
            out[NB * NL + b * NL + t] = active ? 1.f : 0.f;
            s_k = bk;
            s_coef = active ? __fmul_rn(sgn, decay) : 0.f;
        }
        __syncthreads();
        kp = s_k;
        cp = s_coef;
    }

    // ---- epilogue: apply FINAL step's contribution (lazy chain catch-up) --
    float r0 = s_r[tid];
    float r1 = s_r[tid + 256];
    if (cp != 0.f) {
        float c0 = __ldg(&Cb[(size_t)kp * ND + tid]);
        float c1 = __ldg(&Cb[(size_t)kp * ND + tid + 256]);
        r0 = __fsub_rn(r0, __fmul_rn(cp, c0));
        r1 = __fsub_rn(r1, __fmul_rn(cp, c1));
    }
    float* out_res = out + (size_t)2 * NB * NL;
    out_res[(size_t)b * ND + tid]       = r0;
    out_res[(size_t)b * ND + tid + 256] = r1;
}

// ---------------- launch ----------------------------------------------------
extern "C" void kernel_launch(void* const* d_in, const int* in_sizes, int n_in,
                              void* d_out, int out_size) {
    const float* targets  = (const float*)d_in[0];  // [8192, 512]
    const float* codebook = (const float*)d_in[1];  // [4096, 512]
    float* out = (float*)d_out;

    float *pS, *pG;
    cudaGetSymbolAddress((void**)&pS, g_S);
    cudaGetSymbolAddress((void**)&pG, g_G);

    dim3 gS(NK / BN, NB / BM);
    sgemm_nt_kernel<<<gS, 256>>>(targets, codebook, pS, NB, NK, ND);

    dim3 gG(NK / BN, NK / BM);
    sgemm_nt_kernel<<<gG, 256>>>(codebook, codebook, pG, NK, NK, ND);

    pursuit_kernel<<<NB, 256>>>(targets, codebook, pG, pS, out);
}

// round 9
// speedup vs baseline: 2.1514x; 1.1905x over previous
#include <cuda_runtime.h>
#include <math.h>
#include <stdint.h>

#define NB 8192     // batch
#define ND 512      // dim
#define NK 4096     // codebook size
#define NL 16       // max word length

// ---------------- scratch (device globals) ---------------------------------
__device__ float g_S[(size_t)NB * NK];   // scores s0[b,k] (tf32 GEMM, nomination only)
__device__ float g_G[(size_t)NK * NK];   // gram G[i,j] (tf32 GEMM, nomination only)

// ---------------- tf32 helpers ---------------------------------------------
__device__ __forceinline__ uint32_t cvt_tf32(float x) {
    uint32_t y;
    asm("cvt.rna.tf32.f32 %0, %1;" : "=r"(y) : "f"(x));
    return y;
}
__device__ __forceinline__ void mma_tf32(float* d, const uint32_t* a,
                                         uint32_t b0, uint32_t b1) {
    asm volatile(
        "mma.sync.aligned.m16n8k8.row.col.f32.tf32.tf32.f32 "
        "{%0,%1,%2,%3}, {%4,%5,%6,%7}, {%8,%9}, {%0,%1,%2,%3};\n"
        : "+f"(d[0]), "+f"(d[1]), "+f"(d[2]), "+f"(d[3])
        : "r"(a[0]), "r"(a[1]), "r"(a[2]), "r"(a[3]), "r"(b0), "r"(b1));
}

// ---------------- tf32 GEMM (NT): C[M,N] = A[M,K] * B[N,K]^T ---------------
// 128x128x32 tiles, 256 threads = 8 warps (4x2), warp tile 32x64 (2x8 mmas).
// smem layout [row][32+4] (stride 36): STS.128 and fragment LDS conflict-free.
#define TBM 128
#define TBN 128
#define TBK 32
#define TST 36   // smem row stride (floats)

__global__ __launch_bounds__(256, 2)
void tf32_gemm_nt(const float* __restrict__ A, const float* __restrict__ Bm,
                  float* __restrict__ Cc, int M, int N, int Kd) {
    __shared__ uint32_t As[TBM][TST];
    __shared__ uint32_t Bs[TBN][TST];
    int tid = threadIdx.x;
    int lane = tid & 31, wid = tid >> 5;
    int warp_m = wid >> 1;          // 0..3
    int warp_n = wid & 1;           // 0..1
    int gid = lane >> 2;            // 0..7
    int tig = lane & 3;             // 0..3
    int m0 = blockIdx.y * TBM, n0 = blockIdx.x * TBN;

    float acc[2][8][4];
    #pragma unroll
    for (int i = 0; i < 2; i++)
        #pragma unroll
        for (int j = 0; j < 8; j++)
            #pragma unroll
            for (int c = 0; c < 4; c++) acc[i][j][c] = 0.f;

    for (int d0 = 0; d0 < Kd; d0 += TBK) {
        #pragma unroll
        for (int i = 0; i < 4; i++) {
            int idx = tid + i * 256;        // 0..1023
            int r  = idx >> 3;              // 0..127
            int cg = (idx & 7) << 2;        // 0..28
            float4 va = *(const float4*)&A[(size_t)(m0 + r) * Kd + d0 + cg];
            uint4 ua = make_uint4(cvt_tf32(va.x), cvt_tf32(va.y),
                                  cvt_tf32(va.z), cvt_tf32(va.w));
            *(uint4*)&As[r][cg] = ua;
            float4 vb = *(const float4*)&Bm[(size_t)(n0 + r) * Kd + d0 + cg];
            uint4 ub = make_uint4(cvt_tf32(vb.x), cvt_tf32(vb.y),
                                  cvt_tf32(vb.z), cvt_tf32(vb.w));
            *(uint4*)&Bs[r][cg] = ub;
        }
        __syncthreads();

        #pragma unroll
        for (int k8 = 0; k8 < 4; k8++) {
            int ko = k8 * 8;
            uint32_t af[2][4];
            #pragma unroll
            for (int i = 0; i < 2; i++) {
                int mo = warp_m * 32 + i * 16;
                af[i][0] = As[mo + gid    ][ko + tig    ];
                af[i][1] = As[mo + gid + 8][ko + tig    ];
                af[i][2] = As[mo + gid    ][ko + tig + 4];
                af[i][3] = As[mo + gid + 8][ko + tig + 4];
            }
            #pragma unroll
            for (int j = 0; j < 8; j++) {
                int no = warp_n * 64 + j * 8;
                uint32_t b0 = Bs[no + gid][ko + tig    ];
                uint32_t b1 = Bs[no + gid][ko + tig + 4];
                mma_tf32(acc[0][j], af[0], b0, b1);
                mma_tf32(acc[1][j], af[1], b0, b1);
            }
        }
        __syncthreads();
    }

    #pragma unroll
    for (int i = 0; i < 2; i++) {
        int m = m0 + warp_m * 32 + i * 16 + gid;
        #pragma unroll
        for (int j = 0; j < 8; j++) {
            int n = n0 + warp_n * 64 + j * 8 + 2 * tig;
            *(float2*)&Cc[(size_t)m * N + n] =
                make_float2(acc[i][j][0], acc[i][j][1]);
            *(float2*)&Cc[(size_t)(m + 8) * N + n] =
                make_float2(acc[i][j][2], acc[i][j][3]);
        }
    }
}

// ---------------- fused pursuit: 16 steps + finalize, one kernel -----------
// Decision-path arithmetic byte-identical to round-7 (passing) kernel:
// unfused residual update, fp64 left-to-right rho combine, elementwise
// __fdiv_rn, sequential fp32 fmaf rescore chains. Nomination (approx scores)
// widened to top-4 via packed-u64 top-2 per thread -> warp -> block select.
__global__ __launch_bounds__(256)
void pursuit_kernel(const float* __restrict__ T, const float* __restrict__ Cb,
                    const float* __restrict__ G, const float* __restrict__ S0,
                    float* __restrict__ out) {
    __shared__ float  sS[NK];            // 16 KB score row
    __shared__ float  s_r[ND];           // residual
    __shared__ float  s_q[ND];           // r / max(rho,1e-12)
    __shared__ float  s_cr[4][ND];       // staged candidate rows (8 KB)
    __shared__ double s_red[8];
    __shared__ unsigned long long s_w64[16];
    __shared__ int    s_cand[4];
    __shared__ float  s_coef;
    __shared__ int    s_k;

    int b = blockIdx.x;
    int tid = threadIdx.x;
    int lane = tid & 31;
    int wid = tid >> 5;

    #pragma unroll
    for (int it = 0; it < 4; it++) {
        int k = tid * 4 + it * 1024;
        *(float4*)&sS[k] = *(const float4*)&S0[(size_t)b * NK + k];
    }
    s_r[tid]       = T[(size_t)b * ND + tid];
    s_r[tid + 256] = T[(size_t)b * ND + tid + 256];
    __syncthreads();

    int kp = 0; float cp = 0.f;
    float tn = 0.f;
    double dd = 1.0;

    for (int t = 0; t < NL; t++) {
        dd *= 0.95;                 // double cumprod (same bits as before)
        float decay = (float)dd;

        // ---- phase 1: residual update + fp64 sumsq (identical ops) -------
        double ss = 0.0;
        #pragma unroll
        for (int i = 0; i < 2; i++) {
            int d = tid + i * 256;
            float r = s_r[d];
            if (cp != 0.f) {
                float c = __ldg(&Cb[(size_t)kp * ND + d]);
                r = __fsub_rn(r, __fmul_rn(cp, c));   // unfused: matches jax
                s_r[d] = r;
            }
            s_q[d] = r;
            ss += (double)r * (double)r;
        }
        #pragma unroll
        for (int o = 16; o > 0; o >>= 1)
            ss += __shfl_down_sync(0xffffffffu, ss, o);
        if (lane == 0) s_red[wid] = ss;

        // ---- phase 2: S update (fmaf, identical) + packed-u64 top-2 ------
        unsigned long long p1 = 0ull, p2 = 0ull;
        const float* grow = G + (size_t)kp * NK;
        #pragma unroll
        for (int it = 0; it < 4; it++) {
            int k = tid * 4 + it * 1024;
            float4 s4 = *(float4*)&sS[k];
            if (cp != 0.f) {
                float4 g4 = __ldg((const float4*)&grow[k]);
                s4.x = fmaf(-cp, g4.x, s4.x);
                s4.y = fmaf(-cp, g4.y, s4.y);
                s4.z = fmaf(-cp, g4.z, s4.z);
                s4.w = fmaf(-cp, g4.w, s4.w);
                *(float4*)&sS[k] = s4;
            }
            #pragma unroll
            for (int e = 0; e < 4; e++) {
                float a = fabsf((&s4.x)[e]);
                unsigned long long u =
                    ((unsigned long long)__float_as_uint(a) << 32) |
                    (unsigned)(NK - 1 - (k + e));
                if (u > p1)      { p2 = p1; p1 = u; }
                else if (u > p2) { p2 = u; }
            }
        }
        // warp top-2 merge (butterfly)
        #pragma unroll
        for (int o = 16; o > 0; o >>= 1) {
            unsigned long long q1 = __shfl_xor_sync(0xffffffffu, p1, o);
            unsigned long long q2 = __shfl_xor_sync(0xffffffffu, p2, o);
            if (q1 > p1) { p2 = (p1 > q2) ? p1 : q2; p1 = q1; }
            else         { p2 = (p2 > q1) ? p2 : q1; }
        }
        if (lane == 0) {
            s_w64[wid * 2]     = p1;
            s_w64[wid * 2 + 1] = p2;
        }
        __syncthreads();   // B1

        // ---- rho (all threads, identical left-to-right fp64 order) ------
        double tot = s_red[0] + s_red[1] + s_red[2] + s_red[3]
                   + s_red[4] + s_red[5] + s_red[6] + s_red[7];
        float rho = sqrtf((float)tot);
        if (t == 0) tn = rho;

        // ---- top-4 candidate select (single thread, overlaps rho chains) -
        if (tid == 0) {
            unsigned used = 0;
            #pragma unroll
            for (int c = 0; c < 4; c++) {
                unsigned long long best = 0ull; int bi = 0;
                #pragma unroll
                for (int i = 0; i < 16; i++) {
                    if (!((used >> i) & 1u) && s_w64[i] > best) {
                        best = s_w64[i]; bi = i;
                    }
                }
                used |= 1u << bi;
                s_cand[c] = (NK - 1) - (int)(unsigned)(best & 0xffffffffull);
            }
        }
        __syncthreads();   // B2

        // ---- q-divide (identical) + stage 4 candidate rows ---------------
        {
            float den = fmaxf(rho, 1e-12f);
            int c0 = s_cand[0], c1 = s_cand[1], c2 = s_cand[2], c3 = s_cand[3];
            #pragma unroll
            for (int i = 0; i < 2; i++) {
                int d = tid + i * 256;
                s_q[d] = __fdiv_rn(s_q[d], den);
                s_cr[0][d] = __ldg(&Cb[(size_t)c0 * ND + d]);
                s_cr[1][d] = __ldg(&Cb[(size_t)c1 * ND + d]);
                s_cr[2][d] = __ldg(&Cb[(size_t)c2 * ND + d]);
                s_cr[3][d] = __ldg(&Cb[(size_t)c3 * ND + d]);
            }
        }
        __syncthreads();   // B3

        // ---- rescore (byte-identical sequential fp32 fmaf chains) --------
        float accd = 0.f;
        if (tid < 4) {
            const float* crow = s_cr[tid];
            #pragma unroll 8
            for (int d = 0; d < ND; d++)
                accd = fmaf(s_q[d], crow[d], accd);
        }
        if (wid == 0) {
            float d0 = __shfl_sync(0xffffffffu, accd, 0);
            float d1 = __shfl_sync(0xffffffffu, accd, 1);
            float d2 = __shfl_sync(0xffffffffu, accd, 2);
            float d3 = __shfl_sync(0xffffffffu, accd, 3);
            if (lane == 0) {
                float dots[4] = {d0, d1, d2, d3};
                int bk = s_cand[0]; float sb = dots[0]; float ab = fabsf(sb);
                #pragma unroll
                for (int j = 1; j < 4; j++) {
                    float aj = fabsf(dots[j]); int kj = s_cand[j];
                    if (aj > ab || (aj == ab && kj < bk)) {
                        ab = aj; sb = dots[j]; bk = kj;
                    }
                }
                bool active = (rho >= 0.01f) && (tn >= 1e-8f);
                float sgn = (sb >= 0.f) ? 1.f : -1.f;
                int sidx  = (sb >= 0.f) ? bk : -(bk + 1);
                out[b * NL + t]           = (float)(active ? sidx : 0);
                out[NB * NL + b * NL + t] = active ? 1.f : 0.f;
                s_k = bk;
                s_coef = active ? __fmul_rn(sgn, decay) : 0.f;
            }
        }
        __syncthreads();   // B4
        kp = s_k;
        cp = s_coef;
    }

    // ---- epilogue: apply FINAL step's contribution (identical ops) -------
    float r0 = s_r[tid];
    float r1 = s_r[tid + 256];
    if (cp != 0.f) {
        float c0 = __ldg(&Cb[(size_t)kp * ND + tid]);
        float c1 = __ldg(&Cb[(size_t)kp * ND + tid + 256]);
        r0 = __fsub_rn(r0, __fmul_rn(cp, c0));
        r1 = __fsub_rn(r1, __fmul_rn(cp, c1));
    }
    float* out_res = out + (size_t)2 * NB * NL;
    out_res[(size_t)b * ND + tid]       = r0;
    out_res[(size_t)b * ND + tid + 256] = r1;
}

// ---------------- launch ----------------------------------------------------
extern "C" void kernel_launch(void* const* d_in, const int* in_sizes, int n_in,
                              void* d_out, int out_size) {
    const float* targets  = (const float*)d_in[0];  // [8192, 512]
    const float* codebook = (const float*)d_in[1];  // [4096, 512]
    float* out = (float*)d_out;

    float *pS, *pG;
    cudaGetSymbolAddress((void**)&pS, g_S);
    cudaGetSymbolAddress((void**)&pG, g_G);

    dim3 gS(NK / TBN, NB / TBM);
    tf32_gemm_nt<<<gS, 256>>>(targets, codebook, pS, NB, NK, ND);

    dim3 gG(NK / TBN, NK / TBM);
    tf32_gemm_nt<<<gG, 256>>>(codebook, codebook, pG, NK, NK, ND);

    pursuit_kernel<<<NB, 256>>>(targets, codebook, pG, pS, out);
}